// round 14
// baseline (speedup 1.0000x reference)
#include <cuda_runtime.h>
#include <cuda_fp16.h>
#include <math.h>
#include <stdint.h>

// GCN: 4 layers over N=100000 nodes, E=3200000 edges.
// CSR-by-col build per launch; warp-per-node aggregation gathering from fp16
// activation tables (fp32 accumulate), fp16 aggregates. Aggregation geometry
// = R8 optimum (8 lanes/edge uint4, 8 edges in flight). Histogram uses ONE
// packed 64-bit atomic per edge (count | 2^20 fixed-point weighted degree);
// the atomic's RETURN VALUE provides each edge's within-node rank, so CSR
// placement needs NO atomics at all.

#define NMAX 100000
#define EMAX 3200000
#define PACK_SCALE 1048576.0f           // 2^20
#define PACK_INV   (1.0f / 1048576.0f)
#define PACK_MASK  0xFFFFFFFFFFFFULL    // low 48 bits

// ---------------- scratch (static __device__, no allocations) ----------------
__device__ int   g_is64;
__device__ unsigned long long g_pack[NMAX + 4];  // {cnt:16 | degw_fx:48}
__device__ float g_dinvw[NMAX];
__device__ float g_dinv1[NMAX];
__device__ int   g_indptr[NMAX + 1];
__device__ int   g_bsum[128];
__device__ int   g_rank[EMAX];          // within-node rank of each edge
__device__ int2  g_mw[EMAX];            // {row, __float_as_int(dinvw[row]*w)}
__device__ float g_h0[NMAX * 8];
__device__ __half g_H[NMAX * 64];       // fp16 activation table (h1, then h2)
__device__ __half g_Agg[NMAX * 64];     // fp16 aggregate buffer
__device__ float g_s1[NMAX];            // dinv1[n] * (h3[n] . Wout)

// ---------------- helpers ----------------
__device__ __forceinline__ float softplus_f(float x) {
    return fmaxf(x, 0.f) + log1pf(expf(-fabsf(x)));
}

__device__ __forceinline__ float warp_sum(float v) {
    #pragma unroll
    for (int off = 16; off > 0; off >>= 1)
        v += __shfl_down_sync(0xFFFFFFFFu, v, off);
    return v;
}

// accumulate 8 fp16 features (one uint4) into 8 fp32 accumulators
__device__ __forceinline__ void acc8(float* acc, float c, uint4 u) {
    float2 a = __half22float2(*(const __half2*)&u.x);
    float2 b = __half22float2(*(const __half2*)&u.y);
    float2 d = __half22float2(*(const __half2*)&u.z);
    float2 f = __half22float2(*(const __half2*)&u.w);
    acc[0] = fmaf(c, a.x, acc[0]); acc[1] = fmaf(c, a.y, acc[1]);
    acc[2] = fmaf(c, b.x, acc[2]); acc[3] = fmaf(c, b.y, acc[3]);
    acc[4] = fmaf(c, d.x, acc[4]); acc[5] = fmaf(c, d.y, acc[5]);
    acc[6] = fmaf(c, f.x, acc[6]); acc[7] = fmaf(c, f.y, acc[7]);
}

// pack two fp32 into one __half2 as uint
__device__ __forceinline__ uint32_t pack_h2(float lo, float hi) {
    __half2 h = __floats2half2_rn(lo, hi);
    return *(uint32_t*)&h;
}

// ---------------- kernels ----------------

// Zero histogram; block 0 additionally detects int64 vs int32 edge_index.
__global__ void k_init_detect(const int* __restrict__ p, int n) {
    int i = blockIdx.x * blockDim.x + threadIdx.x;
    if (i < n) g_pack[i] = 0ULL;
    if (blockIdx.x == 0) {
        __shared__ int zc;
        if (threadIdx.x == 0) zc = 0;
        __syncthreads();
        int local = 0;
        for (int j = threadIdx.x; j < 1024; j += blockDim.x)
            if (p[2 * j + 1] == 0) local++;
        atomicAdd(&zc, local);
        __syncthreads();
        if (threadIdx.x == 0) g_is64 = (zc > 1000) ? 1 : 0;
    }
}

// Pass 1: histogram with ONE packed 64-bit atomic per edge; the returned
// pre-add count is this edge's within-node rank (stored coalesced).
__global__ void k_convert(const void* __restrict__ idx,
                          const float* __restrict__ dist, int E) {
    int e = blockIdx.x * blockDim.x + threadIdx.x;
    if (e >= E) return;
    int c;
    if (g_is64) c = (int)((const long long*)idx)[e + E];
    else        c = ((const int*)idx)[e + E];
    float w = 1.0f / (dist[e] + 1e-6f);
    unsigned long long v = (1ULL << 48) +
        (unsigned long long)(w * PACK_SCALE + 0.5f);
    unsigned long long old = atomicAdd(&g_pack[c], v);
    g_rank[e] = (int)(old >> 48);
}

// Scan stage A: per-block sums of counts (extracted from packed histogram).
__global__ void k_bsum(int n) {
    int t = threadIdx.x;
    int i0 = blockIdx.x * 1024 + t * 4;
    int s = 0;
    if (i0 + 3 < n) {
        ulonglong2 a = *(const ulonglong2*)&g_pack[i0];
        ulonglong2 b = *(const ulonglong2*)&g_pack[i0 + 2];
        s = (int)(a.x >> 48) + (int)(a.y >> 48)
          + (int)(b.x >> 48) + (int)(b.y >> 48);
    } else {
        #pragma unroll
        for (int j = 0; j < 4; j++) {
            int i = i0 + j;
            if (i < n) s += (int)(g_pack[i] >> 48);
        }
    }
    #pragma unroll
    for (int off = 16; off > 0; off >>= 1)
        s += __shfl_down_sync(0xFFFFFFFFu, s, off);
    __shared__ int ws[8];
    if ((t & 31) == 0) ws[t >> 5] = s;
    __syncthreads();
    if (t == 0) {
        int tot = 0;
        #pragma unroll
        for (int k = 0; k < 8; k++) tot += ws[k];
        g_bsum[blockIdx.x] = tot;
    }
}

// Scan stage B (inlined per block) + fused per-node work:
// indptr, dinvw/dinv1 (self-loop folded), H0 build.
__global__ void k_fill(const float* __restrict__ x,
                       const float* __restrict__ dtr,
                       const float* __restrict__ npd,
                       const float* __restrict__ kp,
                       const float* __restrict__ kpp,
                       const float* __restrict__ imin,
                       const float* __restrict__ imax, int n, int nb) {
    __shared__ int sh[128];
    int t = threadIdx.x;
    if (t < 128) sh[t] = (t < nb) ? g_bsum[t] : 0;
    __syncthreads();
    #pragma unroll
    for (int off = 1; off < 128; off <<= 1) {
        int u = (t < 128 && t >= off) ? sh[t - off] : 0;
        __syncthreads();
        if (t < 128) sh[t] += u;
        __syncthreads();
    }
    __shared__ int blockExcl, totalE;
    if (t == 0) {
        blockExcl = (blockIdx.x == 0) ? 0 : sh[blockIdx.x - 1];
        totalE = sh[nb - 1];
    }
    __syncthreads();

    int lane = t & 31;
    int warp = t >> 5;
    int i0 = blockIdx.x * 1024 + t * 4;

    unsigned long long pv[4];
    int c[4];
    #pragma unroll
    for (int j = 0; j < 4; j++) {
        int i = i0 + j;
        pv[j] = (i < n) ? g_pack[i] : 0ULL;
        c[j] = (int)(pv[j] >> 48);
    }
    int tsum = c[0] + c[1] + c[2] + c[3];

    int inc = tsum;
    #pragma unroll
    for (int off = 1; off < 32; off <<= 1) {
        int u = __shfl_up_sync(0xFFFFFFFFu, inc, off);
        if (lane >= off) inc += u;
    }
    __shared__ int wsum[8];
    if (lane == 31) wsum[warp] = inc;
    __syncthreads();
    int woff = 0;
    for (int k = 0; k < warp; k++) woff += wsum[k];

    int excl = blockExcl + woff + (inc - tsum);
    #pragma unroll
    for (int j = 0; j < 4; j++) {
        int i = i0 + j;
        if (i < n) {
            g_indptr[i] = excl;
            float degw = (float)(pv[j] & PACK_MASK) * PACK_INV;
            g_dinvw[i] = rsqrtf(degw + 1.0f);        // self-loop weight 1
            g_dinv1[i] = rsqrtf((float)c[j] + 1.f);
            float2 xv = ((const float2*)x)[i];
            float4 a = make_float4(xv.x, xv.y, dtr[i], npd[i]);
            float4 b = make_float4(kp[i], kpp[i], imin[i], imax[i]);
            ((float4*)g_h0)[2 * i] = a;
            ((float4*)g_h0)[2 * i + 1] = b;
            if (i == n - 1) g_indptr[n] = totalE;
            excl += c[j];
        }
    }
}

// Pass 2: place edges into CSR order — ATOMIC-FREE (pos = indptr + rank).
__global__ void k_place(const void* __restrict__ idx,
                        const float* __restrict__ dist, int E) {
    int e = blockIdx.x * blockDim.x + threadIdx.x;
    if (e >= E) return;
    int r, c;
    if (g_is64) {
        const long long* p = (const long long*)idx;
        r = (int)p[e];
        c = (int)p[e + E];
    } else {
        const int* p = (const int*)idx;
        r = p[e];
        c = p[e + E];
    }
    float w = 1.0f / (dist[e] + 1e-6f);
    int pos = g_indptr[c] + g_rank[e];
    g_mw[pos] = make_int2(r, __float_as_int(g_dinvw[r] * w));
}

// Layer 1 fused: aggregate 8-feature H0 (warp per node, 8 edges/iter in two
// independent chains), then in-warp GEMM(8->64)+bias+softplus -> fp16 h1.
__global__ __launch_bounds__(256) void k_agg8_gemm1(
        const float* __restrict__ W1, const float* __restrict__ b1,
        __half* __restrict__ outH, int n) {
    __shared__ float w1s[8 * 64];
    __shared__ float b1s[64];
    int t = threadIdx.x;
    for (int i = t; i < 512; i += 256) w1s[i] = W1[i];
    if (t < 64) b1s[t] = b1[t];
    __syncthreads();

    int w = (blockIdx.x * 256 + t) >> 5;
    if (w >= n) return;
    int lane = t & 31;
    int g = lane >> 3;
    int f = lane & 7;
    int beg = g_indptr[w], end = g_indptr[w + 1];
    float acc = 0.f;
    int e = beg;
    for (; e + 8 <= end; e += 8) {
        int2 m0 = __ldg(&g_mw[e + g]);
        int2 m1 = __ldg(&g_mw[e + 4 + g]);
        float v0 = g_h0[m0.x * 8 + f];
        float v1 = g_h0[m1.x * 8 + f];
        acc = fmaf(__int_as_float(m0.y), v0, acc);
        acc = fmaf(__int_as_float(m1.y), v1, acc);
    }
    for (; e < end; e += 4) {
        int ee = e + g;
        if (ee < end) {
            int2 m = __ldg(&g_mw[ee]);
            acc += __int_as_float(m.y) * g_h0[m.x * 8 + f];
        }
    }
    acc += __shfl_xor_sync(0xFFFFFFFFu, acc, 8);
    acc += __shfl_xor_sync(0xFFFFFFFFu, acc, 16);
    float dv = g_dinvw[w];
    float val = dv * (acc + dv * g_h0[w * 8 + f]);   // lane holds f = lane&7

    float a[8];
    #pragma unroll
    for (int k = 0; k < 8; k++) a[k] = __shfl_sync(0xFFFFFFFFu, val, k);

    float s0 = b1s[lane], s1 = b1s[lane + 32];
    #pragma unroll
    for (int k = 0; k < 8; k++) {
        s0 = fmaf(a[k], w1s[k * 64 + lane], s0);
        s1 = fmaf(a[k], w1s[k * 64 + lane + 32], s1);
    }
    outH[(size_t)w * 64 + lane]      = __float2half_rn(softplus_f(s0));
    outH[(size_t)w * 64 + lane + 32] = __float2half_rn(softplus_f(s1));
}

// Aggregate 64-feature fp16 table -> fp16 aggregate. Warp per node;
// 8 lanes per edge (uint4 = 8 features/lane), 8 edges in flight per
// iteration in two independent chains. fp32 accumulate, fp16 store.
__global__ __launch_bounds__(256) void k_agg64(
        const __half* __restrict__ h, __half* __restrict__ agg, int n) {
    int w = (blockIdx.x * blockDim.x + threadIdx.x) >> 5;
    if (w >= n) return;
    int lane = threadIdx.x & 31;
    int q = lane >> 3;        // quarter: which edge of the group
    int l8 = lane & 7;        // feature block: features [8*l8, 8*l8+8)
    int beg = g_indptr[w], end = g_indptr[w + 1];
    float acc[8] = {0.f, 0.f, 0.f, 0.f, 0.f, 0.f, 0.f, 0.f};
    int e = beg;
    for (; e + 8 <= end; e += 8) {
        int2 m0 = __ldg(&g_mw[e + q]);
        int2 m1 = __ldg(&g_mw[e + 4 + q]);
        uint4 u0 = __ldg((const uint4*)(h + (size_t)m0.x * 64) + l8);
        uint4 u1 = __ldg((const uint4*)(h + (size_t)m1.x * 64) + l8);
        acc8(acc, __int_as_float(m0.y), u0);
        acc8(acc, __int_as_float(m1.y), u1);
    }
    for (; e + 4 <= end; e += 4) {
        int2 m = __ldg(&g_mw[e + q]);
        uint4 u = __ldg((const uint4*)(h + (size_t)m.x * 64) + l8);
        acc8(acc, __int_as_float(m.y), u);
    }
    int rem = end - e;
    if (q < rem) {
        int2 m = __ldg(&g_mw[e + q]);
        uint4 u = __ldg((const uint4*)(h + (size_t)m.x * 64) + l8);
        acc8(acc, __int_as_float(m.y), u);
    }
    // reduce across the 4 quarters
    #pragma unroll
    for (int i = 0; i < 8; i++) {
        acc[i] += __shfl_xor_sync(0xFFFFFFFFu, acc[i], 8);
        acc[i] += __shfl_xor_sync(0xFFFFFFFFu, acc[i], 16);
    }
    if (q == 0) {
        float dv = g_dinvw[w];
        uint4 su = __ldg((const uint4*)(h + (size_t)w * 64) + l8);
        float2 sa = __half22float2(*(const __half2*)&su.x);
        float2 sb = __half22float2(*(const __half2*)&su.y);
        float2 sc = __half22float2(*(const __half2*)&su.z);
        float2 sd = __half22float2(*(const __half2*)&su.w);
        uint4 o;
        o.x = pack_h2(dv * (acc[0] + dv * sa.x), dv * (acc[1] + dv * sa.y));
        o.y = pack_h2(dv * (acc[2] + dv * sb.x), dv * (acc[3] + dv * sb.y));
        o.z = pack_h2(dv * (acc[4] + dv * sc.x), dv * (acc[5] + dv * sc.y));
        o.w = pack_h2(dv * (acc[6] + dv * sd.x), dv * (acc[7] + dv * sd.y));
        ((uint4*)(agg + (size_t)w * 64))[l8] = o;
    }
}

// GEMM [n,64](fp16) x [64,64] + bias + softplus -> fp16 table. W in registers,
// 8-row smem stages (fp16 expanded to fp32 on fill).
__global__ __launch_bounds__(256) void k_gemm64(
        const __half* __restrict__ in, const float* __restrict__ W,
        const float* __restrict__ b, __half* __restrict__ out, int n) {
    __shared__ float sIn[8 * 64];
    int o = threadIdx.x & 63;
    int nl = threadIdx.x >> 6;   // 0..3
    float wreg[64];
    #pragma unroll
    for (int f = 0; f < 64; f++) wreg[f] = W[f * 64 + o];
    float bias = b[o];
    int base = blockIdx.x * 128;
    for (int k = 0; k < 128; k += 8) {
        __syncthreads();
        if (threadIdx.x < 128) {
            int rr = threadIdx.x >> 4;
            int cc = threadIdx.x & 15;
            int node = base + k + rr;
            uint2 u = (node < n) ? __ldg((const uint2*)(in + (size_t)node * 64) + cc)
                                 : make_uint2(0u, 0u);
            float2 fa = __half22float2(*(const __half2*)&u.x);
            float2 fb = __half22float2(*(const __half2*)&u.y);
            ((float4*)sIn)[threadIdx.x] = make_float4(fa.x, fa.y, fb.x, fb.y);
        }
        __syncthreads();
        #pragma unroll
        for (int s = 0; s < 2; s++) {
            int r = nl + s * 4;
            int node = base + k + r;
            if (node < n) {
                float acc = bias;
                #pragma unroll
                for (int f = 0; f < 64; f++) acc = fmaf(sIn[r * 64 + f], wreg[f], acc);
                out[(size_t)node * 64 + o] = __float2half_rn(softplus_f(acc));
            }
        }
    }
}

// Layer-3 GEMM fused with the output projection (input fp16 aggregate):
// s1[node] = dinv1[node] * sum_o softplus(gemm_o) * Wout[o].
__global__ __launch_bounds__(256) void k_gemm_wout(
        const __half* __restrict__ in, const float* __restrict__ W,
        const float* __restrict__ b, const float* __restrict__ Wout, int n) {
    __shared__ float sIn[8 * 64];
    __shared__ float red[8];
    int o = threadIdx.x & 63;
    int nl = threadIdx.x >> 6;   // 0..3
    float wreg[64];
    #pragma unroll
    for (int f = 0; f < 64; f++) wreg[f] = W[f * 64 + o];
    float bias = b[o];
    float wo = Wout[o];
    int base = blockIdx.x * 128;
    for (int k = 0; k < 128; k += 8) {
        __syncthreads();
        if (threadIdx.x < 128) {
            int rr = threadIdx.x >> 4;
            int cc = threadIdx.x & 15;
            int node = base + k + rr;
            uint2 u = (node < n) ? __ldg((const uint2*)(in + (size_t)node * 64) + cc)
                                 : make_uint2(0u, 0u);
            float2 fa = __half22float2(*(const __half2*)&u.x);
            float2 fb = __half22float2(*(const __half2*)&u.y);
            ((float4*)sIn)[threadIdx.x] = make_float4(fa.x, fa.y, fb.x, fb.y);
        }
        __syncthreads();
        #pragma unroll
        for (int s = 0; s < 2; s++) {
            int r = nl + s * 4;
            int node = base + k + r;
            float part = 0.f;
            if (node < n) {
                float acc = bias;
                #pragma unroll
                for (int f = 0; f < 64; f++) acc = fmaf(sIn[r * 64 + f], wreg[f], acc);
                part = softplus_f(acc) * wo;
            }
            float ws = warp_sum(part);
            if ((threadIdx.x & 31) == 0) red[threadIdx.x >> 5] = ws;
            __syncthreads();
            if (o == 0 && node < n)
                g_s1[node] = g_dinv1[node] * (red[nl * 2] + red[nl * 2 + 1]);
            __syncthreads();
        }
    }
}

// out[n] = bout + dinv1[n] * (s1[n] + sum_e s1[row[e]])   (warp per node)
__global__ __launch_bounds__(256) void k_out(
        const float* __restrict__ bout, float* __restrict__ out, int n) {
    int w = (blockIdx.x * blockDim.x + threadIdx.x) >> 5;
    if (w >= n) return;
    int lane = threadIdx.x & 31;
    int beg = g_indptr[w], end = g_indptr[w + 1];
    float acc = 0.f;
    for (int e = beg + lane; e < end; e += 32) {
        int r = __ldg(&g_mw[e]).x;
        acc += g_s1[r];
    }
    acc = warp_sum(acc);
    if (lane == 0)
        out[w] = bout[0] + g_dinv1[w] * (acc + g_s1[w]);
}

// ---------------- launch ----------------
extern "C" void kernel_launch(void* const* d_in, const int* in_sizes, int n_in,
                              void* d_out, int out_size) {
    (void)n_in; (void)out_size;
    const void*  edge_idx = d_in[8];
    const float* edge_d   = (const float*)d_in[9];
    const float* x    = (const float*)d_in[1];
    const float* dtr  = (const float*)d_in[2];
    const float* npd  = (const float*)d_in[3];
    const float* kp   = (const float*)d_in[4];
    const float* kpp  = (const float*)d_in[5];
    const float* imin = (const float*)d_in[6];
    const float* imax = (const float*)d_in[7];
    const float* W1 = (const float*)d_in[10];
    const float* b1 = (const float*)d_in[11];
    const float* W2 = (const float*)d_in[12];
    const float* b2 = (const float*)d_in[13];
    const float* W3 = (const float*)d_in[14];
    const float* b3 = (const float*)d_in[15];
    const float* Wout = (const float*)d_in[16];
    const float* bout = (const float*)d_in[17];

    int N = in_sizes[1] / 2;          // x is [N,2]
    int E = in_sizes[9];              // edge_distance is [E]
    if (N > NMAX) N = NMAX;
    if (E > EMAX) E = EMAX;

    __half *pH = nullptr, *pAgg = nullptr;
    cudaGetSymbolAddress((void**)&pH, g_H);
    cudaGetSymbolAddress((void**)&pAgg, g_Agg);

    const int T = 256;
    int gN  = (N + T - 1) / T;
    int gE  = (E + T - 1) / T;
    int gW  = (N * 32 + T - 1) / T;       // warp-per-node kernels
    int gG  = (N + 127) / 128;            // gemm blocks
    int nb  = (N + 1023) / 1024;          // scan blocks

    k_init_detect<<<gN, T>>>((const int*)edge_idx, N);
    k_convert<<<gE, T>>>(edge_idx, edge_d, E);
    k_bsum<<<nb, 256>>>(N);
    k_fill<<<nb, 256>>>(x, dtr, npd, kp, kpp, imin, imax, N, nb);
    k_place<<<gE, T>>>(edge_idx, edge_d, E);

    // Layer 1: fused aggregate(8) + GEMM(8->64) + softplus -> fp16 table (h1)
    k_agg8_gemm1<<<gW, T>>>(W1, b1, pH, N);

    // Layer 2: gather fp16 h1 -> fp16 aggregate -> GEMM -> fp16 table (h2)
    k_agg64<<<gW, T>>>(pH, pAgg, N);
    k_gemm64<<<gG, 256>>>(pAgg, W2, b2, pH, N);

    // Layer 3: gather fp16 h2 -> fp16 aggregate -> GEMM + output projection
    k_agg64<<<gW, T>>>(pH, pAgg, N);
    k_gemm_wout<<<gG, 256>>>(pAgg, W3, b3, Wout, N);

    // Output conv aggregation with ones-norms
    k_out<<<gW, T>>>(bout, (float*)d_out, N);
}

// round 15
// speedup vs baseline: 1.0170x; 1.0170x over previous
#include <cuda_runtime.h>
#include <cuda_fp16.h>
#include <math.h>
#include <stdint.h>

// GCN: 4 layers over N=100000 nodes, E=3200000 edges.
// CSR-by-col build per launch; warp-per-node aggregation gathering from fp16
// activation tables (fp32 accumulate), fp16 aggregates. Aggregation geometry
// = R8 optimum (8 lanes/edge uint4, 8 edges in flight). Histogram uses ONE
// packed 64-bit atomic per edge: count in bits [48:64), weighted degree as
// 2^20 fixed point in bits [0:48). Placement uses plain cursor atomics
// (fire-and-forget; R14 showed the return-value variant is slower).

#define NMAX 100000
#define EMAX 3200000
#define PACK_SCALE 1048576.0f           // 2^20
#define PACK_INV   (1.0f / 1048576.0f)
#define PACK_MASK  0xFFFFFFFFFFFFULL    // low 48 bits

// ---------------- scratch (static __device__, no allocations) ----------------
__device__ int   g_is64;
__device__ unsigned long long g_pack[NMAX + 4];  // {cnt:16 | degw_fx:48}
__device__ float g_dinvw[NMAX];
__device__ float g_dinv1[NMAX];
__device__ int   g_indptr[NMAX + 1];
__device__ int   g_cursor[NMAX];
__device__ int   g_bsum[128];
__device__ int2  g_mw[EMAX];            // {row, __float_as_int(dinvw[row]*w)}
__device__ float g_h0[NMAX * 8];
__device__ __half g_H[NMAX * 64];       // fp16 activation table (h1, then h2)
__device__ __half g_Agg[NMAX * 64];     // fp16 aggregate buffer
__device__ float g_s1[NMAX];            // dinv1[n] * (h3[n] . Wout)

// ---------------- helpers ----------------
__device__ __forceinline__ float softplus_f(float x) {
    return fmaxf(x, 0.f) + log1pf(expf(-fabsf(x)));
}

__device__ __forceinline__ float warp_sum(float v) {
    #pragma unroll
    for (int off = 16; off > 0; off >>= 1)
        v += __shfl_down_sync(0xFFFFFFFFu, v, off);
    return v;
}

// accumulate 8 fp16 features (one uint4) into 8 fp32 accumulators
__device__ __forceinline__ void acc8(float* acc, float c, uint4 u) {
    float2 a = __half22float2(*(const __half2*)&u.x);
    float2 b = __half22float2(*(const __half2*)&u.y);
    float2 d = __half22float2(*(const __half2*)&u.z);
    float2 f = __half22float2(*(const __half2*)&u.w);
    acc[0] = fmaf(c, a.x, acc[0]); acc[1] = fmaf(c, a.y, acc[1]);
    acc[2] = fmaf(c, b.x, acc[2]); acc[3] = fmaf(c, b.y, acc[3]);
    acc[4] = fmaf(c, d.x, acc[4]); acc[5] = fmaf(c, d.y, acc[5]);
    acc[6] = fmaf(c, f.x, acc[6]); acc[7] = fmaf(c, f.y, acc[7]);
}

// pack two fp32 into one __half2 as uint
__device__ __forceinline__ uint32_t pack_h2(float lo, float hi) {
    __half2 h = __floats2half2_rn(lo, hi);
    return *(uint32_t*)&h;
}

// ---------------- kernels ----------------

// Zero histogram; block 0 additionally detects int64 vs int32 edge_index.
__global__ void k_init_detect(const int* __restrict__ p, int n) {
    int i = blockIdx.x * blockDim.x + threadIdx.x;
    if (i < n) g_pack[i] = 0ULL;
    if (blockIdx.x == 0) {
        __shared__ int zc;
        if (threadIdx.x == 0) zc = 0;
        __syncthreads();
        int local = 0;
        for (int j = threadIdx.x; j < 1024; j += blockDim.x)
            if (p[2 * j + 1] == 0) local++;
        atomicAdd(&zc, local);
        __syncthreads();
        if (threadIdx.x == 0) g_is64 = (zc > 1000) ? 1 : 0;
    }
}

// Pass 1: histogram with ONE packed 64-bit atomic per edge.
__global__ void k_convert(const void* __restrict__ idx,
                          const float* __restrict__ dist, int E) {
    int e = blockIdx.x * blockDim.x + threadIdx.x;
    if (e >= E) return;
    int c;
    if (g_is64) c = (int)((const long long*)idx)[e + E];
    else        c = ((const int*)idx)[e + E];
    float w = 1.0f / (dist[e] + 1e-6f);
    unsigned long long v = (1ULL << 48) +
        (unsigned long long)(w * PACK_SCALE + 0.5f);
    atomicAdd(&g_pack[c], v);
}

// Scan stage A: per-block sums of counts (extracted from packed histogram).
__global__ void k_bsum(int n) {
    int t = threadIdx.x;
    int i0 = blockIdx.x * 1024 + t * 4;
    int s = 0;
    if (i0 + 3 < n) {
        ulonglong2 a = *(const ulonglong2*)&g_pack[i0];
        ulonglong2 b = *(const ulonglong2*)&g_pack[i0 + 2];
        s = (int)(a.x >> 48) + (int)(a.y >> 48)
          + (int)(b.x >> 48) + (int)(b.y >> 48);
    } else {
        #pragma unroll
        for (int j = 0; j < 4; j++) {
            int i = i0 + j;
            if (i < n) s += (int)(g_pack[i] >> 48);
        }
    }
    #pragma unroll
    for (int off = 16; off > 0; off >>= 1)
        s += __shfl_down_sync(0xFFFFFFFFu, s, off);
    __shared__ int ws[8];
    if ((t & 31) == 0) ws[t >> 5] = s;
    __syncthreads();
    if (t == 0) {
        int tot = 0;
        #pragma unroll
        for (int k = 0; k < 8; k++) tot += ws[k];
        g_bsum[blockIdx.x] = tot;
    }
}

// Scan stage B (single-warp shfl scan of block sums; ONE barrier) + fused
// per-node work: indptr/cursor, dinvw/dinv1 (self-loop folded), H0 build.
__global__ void k_fill(const float* __restrict__ x,
                       const float* __restrict__ dtr,
                       const float* __restrict__ npd,
                       const float* __restrict__ kp,
                       const float* __restrict__ kpp,
                       const float* __restrict__ imin,
                       const float* __restrict__ imax, int n, int nb) {
    __shared__ int sh[128];       // exclusive prefix of block sums
    __shared__ int shTotal;
    int t = threadIdx.x;
    if (t < 32) {                 // warp 0: scan up to 128 block sums
        int b0 = t * 4;
        int v0 = (b0 + 0 < nb) ? g_bsum[b0 + 0] : 0;
        int v1 = (b0 + 1 < nb) ? g_bsum[b0 + 1] : 0;
        int v2 = (b0 + 2 < nb) ? g_bsum[b0 + 2] : 0;
        int v3 = (b0 + 3 < nb) ? g_bsum[b0 + 3] : 0;
        int tsum = v0 + v1 + v2 + v3;
        int inc = tsum;
        #pragma unroll
        for (int off = 1; off < 32; off <<= 1) {
            int u = __shfl_up_sync(0xFFFFFFFFu, inc, off);
            if (t >= off) inc += u;
        }
        int run = inc - tsum;     // exclusive prefix of this lane's group
        sh[b0 + 0] = run; run += v0;
        sh[b0 + 1] = run; run += v1;
        sh[b0 + 2] = run; run += v2;
        sh[b0 + 3] = run;
        if (t == 31) shTotal = inc;
    }
    __syncthreads();
    int blockExcl = sh[blockIdx.x];
    int totalE = shTotal;

    int lane = t & 31;
    int warp = t >> 5;
    int i0 = blockIdx.x * 1024 + t * 4;

    unsigned long long pv[4];
    int c[4];
    #pragma unroll
    for (int j = 0; j < 4; j++) {
        int i = i0 + j;
        pv[j] = (i < n) ? g_pack[i] : 0ULL;
        c[j] = (int)(pv[j] >> 48);
    }
    int tsum = c[0] + c[1] + c[2] + c[3];

    int inc = tsum;
    #pragma unroll
    for (int off = 1; off < 32; off <<= 1) {
        int u = __shfl_up_sync(0xFFFFFFFFu, inc, off);
        if (lane >= off) inc += u;
    }
    __shared__ int wsum[8];
    if (lane == 31) wsum[warp] = inc;
    __syncthreads();
    int woff = 0;
    for (int k = 0; k < warp; k++) woff += wsum[k];

    int excl = blockExcl + woff + (inc - tsum);
    #pragma unroll
    for (int j = 0; j < 4; j++) {
        int i = i0 + j;
        if (i < n) {
            g_indptr[i] = excl;
            g_cursor[i] = excl;
            float degw = (float)(pv[j] & PACK_MASK) * PACK_INV;
            g_dinvw[i] = rsqrtf(degw + 1.0f);        // self-loop weight 1
            g_dinv1[i] = rsqrtf((float)c[j] + 1.f);
            float2 xv = ((const float2*)x)[i];
            float4 a = make_float4(xv.x, xv.y, dtr[i], npd[i]);
            float4 b = make_float4(kp[i], kpp[i], imin[i], imax[i]);
            ((float4*)g_h0)[2 * i] = a;
            ((float4*)g_h0)[2 * i + 1] = b;
            if (i == n - 1) g_indptr[n] = totalE;
            excl += c[j];
        }
    }
}

// Pass 2: place edges into CSR order with precomputed source-side coefficient.
__global__ void k_place(const void* __restrict__ idx,
                        const float* __restrict__ dist, int E) {
    int e = blockIdx.x * blockDim.x + threadIdx.x;
    if (e >= E) return;
    int r, c;
    if (g_is64) {
        const long long* p = (const long long*)idx;
        r = (int)p[e];
        c = (int)p[e + E];
    } else {
        const int* p = (const int*)idx;
        r = p[e];
        c = p[e + E];
    }
    float w = 1.0f / (dist[e] + 1e-6f);
    int pos = atomicAdd(&g_cursor[c], 1);
    g_mw[pos] = make_int2(r, __float_as_int(g_dinvw[r] * w));
}

// Layer 1 fused: aggregate 8-feature H0 (warp per node, 8 edges/iter in two
// independent chains), then in-warp GEMM(8->64)+bias+softplus -> fp16 h1.
__global__ __launch_bounds__(256) void k_agg8_gemm1(
        const float* __restrict__ W1, const float* __restrict__ b1,
        __half* __restrict__ outH, int n) {
    __shared__ float w1s[8 * 64];
    __shared__ float b1s[64];
    int t = threadIdx.x;
    for (int i = t; i < 512; i += 256) w1s[i] = W1[i];
    if (t < 64) b1s[t] = b1[t];
    __syncthreads();

    int w = (blockIdx.x * 256 + t) >> 5;
    if (w >= n) return;
    int lane = t & 31;
    int g = lane >> 3;
    int f = lane & 7;
    int beg = g_indptr[w], end = g_indptr[w + 1];
    float acc = 0.f;
    int e = beg;
    for (; e + 8 <= end; e += 8) {
        int2 m0 = __ldg(&g_mw[e + g]);
        int2 m1 = __ldg(&g_mw[e + 4 + g]);
        float v0 = g_h0[m0.x * 8 + f];
        float v1 = g_h0[m1.x * 8 + f];
        acc = fmaf(__int_as_float(m0.y), v0, acc);
        acc = fmaf(__int_as_float(m1.y), v1, acc);
    }
    for (; e < end; e += 4) {
        int ee = e + g;
        if (ee < end) {
            int2 m = __ldg(&g_mw[ee]);
            acc += __int_as_float(m.y) * g_h0[m.x * 8 + f];
        }
    }
    acc += __shfl_xor_sync(0xFFFFFFFFu, acc, 8);
    acc += __shfl_xor_sync(0xFFFFFFFFu, acc, 16);
    float dv = g_dinvw[w];
    float val = dv * (acc + dv * g_h0[w * 8 + f]);   // lane holds f = lane&7

    float a[8];
    #pragma unroll
    for (int k = 0; k < 8; k++) a[k] = __shfl_sync(0xFFFFFFFFu, val, k);

    float s0 = b1s[lane], s1 = b1s[lane + 32];
    #pragma unroll
    for (int k = 0; k < 8; k++) {
        s0 = fmaf(a[k], w1s[k * 64 + lane], s0);
        s1 = fmaf(a[k], w1s[k * 64 + lane + 32], s1);
    }
    outH[(size_t)w * 64 + lane]      = __float2half_rn(softplus_f(s0));
    outH[(size_t)w * 64 + lane + 32] = __float2half_rn(softplus_f(s1));
}

// Aggregate 64-feature fp16 table -> fp16 aggregate. Warp per node;
// 8 lanes per edge (uint4 = 8 features/lane), 8 edges in flight per
// iteration in two independent chains. fp32 accumulate, fp16 store.
__global__ __launch_bounds__(256) void k_agg64(
        const __half* __restrict__ h, __half* __restrict__ agg, int n) {
    int w = (blockIdx.x * blockDim.x + threadIdx.x) >> 5;
    if (w >= n) return;
    int lane = threadIdx.x & 31;
    int q = lane >> 3;        // quarter: which edge of the group
    int l8 = lane & 7;        // feature block: features [8*l8, 8*l8+8)
    int beg = g_indptr[w], end = g_indptr[w + 1];
    float acc[8] = {0.f, 0.f, 0.f, 0.f, 0.f, 0.f, 0.f, 0.f};
    int e = beg;
    for (; e + 8 <= end; e += 8) {
        int2 m0 = __ldg(&g_mw[e + q]);
        int2 m1 = __ldg(&g_mw[e + 4 + q]);
        uint4 u0 = __ldg((const uint4*)(h + (size_t)m0.x * 64) + l8);
        uint4 u1 = __ldg((const uint4*)(h + (size_t)m1.x * 64) + l8);
        acc8(acc, __int_as_float(m0.y), u0);
        acc8(acc, __int_as_float(m1.y), u1);
    }
    for (; e + 4 <= end; e += 4) {
        int2 m = __ldg(&g_mw[e + q]);
        uint4 u = __ldg((const uint4*)(h + (size_t)m.x * 64) + l8);
        acc8(acc, __int_as_float(m.y), u);
    }
    int rem = end - e;
    if (q < rem) {
        int2 m = __ldg(&g_mw[e + q]);
        uint4 u = __ldg((const uint4*)(h + (size_t)m.x * 64) + l8);
        acc8(acc, __int_as_float(m.y), u);
    }
    // reduce across the 4 quarters
    #pragma unroll
    for (int i = 0; i < 8; i++) {
        acc[i] += __shfl_xor_sync(0xFFFFFFFFu, acc[i], 8);
        acc[i] += __shfl_xor_sync(0xFFFFFFFFu, acc[i], 16);
    }
    if (q == 0) {
        float dv = g_dinvw[w];
        uint4 su = __ldg((const uint4*)(h + (size_t)w * 64) + l8);
        float2 sa = __half22float2(*(const __half2*)&su.x);
        float2 sb = __half22float2(*(const __half2*)&su.y);
        float2 sc = __half22float2(*(const __half2*)&su.z);
        float2 sd = __half22float2(*(const __half2*)&su.w);
        uint4 o;
        o.x = pack_h2(dv * (acc[0] + dv * sa.x), dv * (acc[1] + dv * sa.y));
        o.y = pack_h2(dv * (acc[2] + dv * sb.x), dv * (acc[3] + dv * sb.y));
        o.z = pack_h2(dv * (acc[4] + dv * sc.x), dv * (acc[5] + dv * sc.y));
        o.w = pack_h2(dv * (acc[6] + dv * sd.x), dv * (acc[7] + dv * sd.y));
        ((uint4*)(agg + (size_t)w * 64))[l8] = o;
    }
}

// GEMM [n,64](fp16) x [64,64] + bias + softplus -> fp16 table. W in registers,
// 8-row smem stages (fp16 expanded to fp32 on fill).
__global__ __launch_bounds__(256) void k_gemm64(
        const __half* __restrict__ in, const float* __restrict__ W,
        const float* __restrict__ b, __half* __restrict__ out, int n) {
    __shared__ float sIn[8 * 64];
    int o = threadIdx.x & 63;
    int nl = threadIdx.x >> 6;   // 0..3
    float wreg[64];
    #pragma unroll
    for (int f = 0; f < 64; f++) wreg[f] = W[f * 64 + o];
    float bias = b[o];
    int base = blockIdx.x * 128;
    for (int k = 0; k < 128; k += 8) {
        __syncthreads();
        if (threadIdx.x < 128) {
            int rr = threadIdx.x >> 4;
            int cc = threadIdx.x & 15;
            int node = base + k + rr;
            uint2 u = (node < n) ? __ldg((const uint2*)(in + (size_t)node * 64) + cc)
                                 : make_uint2(0u, 0u);
            float2 fa = __half22float2(*(const __half2*)&u.x);
            float2 fb = __half22float2(*(const __half2*)&u.y);
            ((float4*)sIn)[threadIdx.x] = make_float4(fa.x, fa.y, fb.x, fb.y);
        }
        __syncthreads();
        #pragma unroll
        for (int s = 0; s < 2; s++) {
            int r = nl + s * 4;
            int node = base + k + r;
            if (node < n) {
                float acc = bias;
                #pragma unroll
                for (int f = 0; f < 64; f++) acc = fmaf(sIn[r * 64 + f], wreg[f], acc);
                out[(size_t)node * 64 + o] = __float2half_rn(softplus_f(acc));
            }
        }
    }
}

// Layer-3 GEMM fused with the output projection (input fp16 aggregate):
// s1[node] = dinv1[node] * sum_o softplus(gemm_o) * Wout[o].
__global__ __launch_bounds__(256) void k_gemm_wout(
        const __half* __restrict__ in, const float* __restrict__ W,
        const float* __restrict__ b, const float* __restrict__ Wout, int n) {
    __shared__ float sIn[8 * 64];
    __shared__ float red[8];
    int o = threadIdx.x & 63;
    int nl = threadIdx.x >> 6;   // 0..3
    float wreg[64];
    #pragma unroll
    for (int f = 0; f < 64; f++) wreg[f] = W[f * 64 + o];
    float bias = b[o];
    float wo = Wout[o];
    int base = blockIdx.x * 128;
    for (int k = 0; k < 128; k += 8) {
        __syncthreads();
        if (threadIdx.x < 128) {
            int rr = threadIdx.x >> 4;
            int cc = threadIdx.x & 15;
            int node = base + k + rr;
            uint2 u = (node < n) ? __ldg((const uint2*)(in + (size_t)node * 64) + cc)
                                 : make_uint2(0u, 0u);
            float2 fa = __half22float2(*(const __half2*)&u.x);
            float2 fb = __half22float2(*(const __half2*)&u.y);
            ((float4*)sIn)[threadIdx.x] = make_float4(fa.x, fa.y, fb.x, fb.y);
        }
        __syncthreads();
        #pragma unroll
        for (int s = 0; s < 2; s++) {
            int r = nl + s * 4;
            int node = base + k + r;
            float part = 0.f;
            if (node < n) {
                float acc = bias;
                #pragma unroll
                for (int f = 0; f < 64; f++) acc = fmaf(sIn[r * 64 + f], wreg[f], acc);
                part = softplus_f(acc) * wo;
            }
            float ws = warp_sum(part);
            if ((threadIdx.x & 31) == 0) red[threadIdx.x >> 5] = ws;
            __syncthreads();
            if (o == 0 && node < n)
                g_s1[node] = g_dinv1[node] * (red[nl * 2] + red[nl * 2 + 1]);
            __syncthreads();
        }
    }
}

// out[n] = bout + dinv1[n] * (s1[n] + sum_e s1[row[e]])   (warp per node)
__global__ __launch_bounds__(256) void k_out(
        const float* __restrict__ bout, float* __restrict__ out, int n) {
    int w = (blockIdx.x * blockDim.x + threadIdx.x) >> 5;
    if (w >= n) return;
    int lane = threadIdx.x & 31;
    int beg = g_indptr[w], end = g_indptr[w + 1];
    float acc = 0.f;
    for (int e = beg + lane; e < end; e += 32) {
        int r = __ldg(&g_mw[e]).x;
        acc += g_s1[r];
    }
    acc = warp_sum(acc);
    if (lane == 0)
        out[w] = bout[0] + g_dinv1[w] * (acc + g_s1[w]);
}

// ---------------- launch ----------------
extern "C" void kernel_launch(void* const* d_in, const int* in_sizes, int n_in,
                              void* d_out, int out_size) {
    (void)n_in; (void)out_size;
    const void*  edge_idx = d_in[8];
    const float* edge_d   = (const float*)d_in[9];
    const float* x    = (const float*)d_in[1];
    const float* dtr  = (const float*)d_in[2];
    const float* npd  = (const float*)d_in[3];
    const float* kp   = (const float*)d_in[4];
    const float* kpp  = (const float*)d_in[5];
    const float* imin = (const float*)d_in[6];
    const float* imax = (const float*)d_in[7];
    const float* W1 = (const float*)d_in[10];
    const float* b1 = (const float*)d_in[11];
    const float* W2 = (const float*)d_in[12];
    const float* b2 = (const float*)d_in[13];
    const float* W3 = (const float*)d_in[14];
    const float* b3 = (const float*)d_in[15];
    const float* Wout = (const float*)d_in[16];
    const float* bout = (const float*)d_in[17];

    int N = in_sizes[1] / 2;          // x is [N,2]
    int E = in_sizes[9];              // edge_distance is [E]
    if (N > NMAX) N = NMAX;
    if (E > EMAX) E = EMAX;

    __half *pH = nullptr, *pAgg = nullptr;
    cudaGetSymbolAddress((void**)&pH, g_H);
    cudaGetSymbolAddress((void**)&pAgg, g_Agg);

    const int T = 256;
    int gN  = (N + T - 1) / T;
    int gE  = (E + T - 1) / T;
    int gW  = (N * 32 + T - 1) / T;       // warp-per-node kernels
    int gG  = (N + 127) / 128;            // gemm blocks
    int nb  = (N + 1023) / 1024;          // scan blocks

    k_init_detect<<<gN, T>>>((const int*)edge_idx, N);
    k_convert<<<gE, T>>>(edge_idx, edge_d, E);
    k_bsum<<<nb, 256>>>(N);
    k_fill<<<nb, 256>>>(x, dtr, npd, kp, kpp, imin, imax, N, nb);
    k_place<<<gE, T>>>(edge_idx, edge_d, E);

    // Layer 1: fused aggregate(8) + GEMM(8->64) + softplus -> fp16 table (h1)
    k_agg8_gemm1<<<gW, T>>>(W1, b1, pH, N);

    // Layer 2: gather fp16 h1 -> fp16 aggregate -> GEMM -> fp16 table (h2)
    k_agg64<<<gW, T>>>(pH, pAgg, N);
    k_gemm64<<<gG, 256>>>(pAgg, W2, b2, pH, N);

    // Layer 3: gather fp16 h2 -> fp16 aggregate -> GEMM + output projection
    k_agg64<<<gW, T>>>(pH, pAgg, N);
    k_gemm_wout<<<gG, 256>>>(pAgg, W3, b3, Wout, N);

    // Output conv aggregation with ones-norms
    k_out<<<gW, T>>>(bout, (float*)d_out, N);
}

// round 16
// speedup vs baseline: 1.0228x; 1.0057x over previous
#include <cuda_runtime.h>
#include <cuda_fp16.h>
#include <math.h>
#include <stdint.h>

// GCN: 4 layers over N=100000 nodes, E=3200000 edges.
// CSR-by-col build per launch; warp-per-node aggregation gathering from fp16
// activation tables (fp32 accumulate), fp16 aggregates, fp16 H0. Aggregation
// geometry = R8 optimum (8 lanes/edge uint4, 8 edges in flight). Histogram
// uses ONE packed 64-bit atomic per edge. int64-vs-int32 edge_index detection
// is inlined per thread (no separate kernel; g_pack zeroed via memset node).

#define NMAX 100000
#define EMAX 3200000
#define PACK_SCALE 1048576.0f           // 2^20
#define PACK_INV   (1.0f / 1048576.0f)
#define PACK_MASK  0xFFFFFFFFFFFFULL    // low 48 bits

// ---------------- scratch (static __device__, no allocations) ----------------
__device__ unsigned long long g_pack[NMAX + 4];  // {cnt:16 | degw_fx:48}
__device__ float g_dinvw[NMAX];
__device__ float g_dinv1[NMAX];
__device__ int   g_indptr[NMAX + 1];
__device__ int   g_cursor[NMAX];
__device__ int   g_bsum[128];
__device__ int2  g_mw[EMAX];            // {row, __float_as_int(dinvw[row]*w)}
__device__ uint4 g_h0[NMAX];            // 8 fp16 features per node (16B)
__device__ __half g_H[NMAX * 64];       // fp16 activation table (h1, then h2)
__device__ __half g_Agg[NMAX * 64];     // fp16 aggregate buffer
__device__ float g_s1[NMAX];            // dinv1[n] * (h3[n] . Wout)

// ---------------- helpers ----------------
__device__ __forceinline__ float softplus_f(float x) {
    return fmaxf(x, 0.f) + log1pf(expf(-fabsf(x)));
}

__device__ __forceinline__ float warp_sum(float v) {
    #pragma unroll
    for (int off = 16; off > 0; off >>= 1)
        v += __shfl_down_sync(0xFFFFFFFFu, v, off);
    return v;
}

// accumulate 8 fp16 features (one uint4) into 8 fp32 accumulators
__device__ __forceinline__ void acc8(float* acc, float c, uint4 u) {
    float2 a = __half22float2(*(const __half2*)&u.x);
    float2 b = __half22float2(*(const __half2*)&u.y);
    float2 d = __half22float2(*(const __half2*)&u.z);
    float2 f = __half22float2(*(const __half2*)&u.w);
    acc[0] = fmaf(c, a.x, acc[0]); acc[1] = fmaf(c, a.y, acc[1]);
    acc[2] = fmaf(c, b.x, acc[2]); acc[3] = fmaf(c, b.y, acc[3]);
    acc[4] = fmaf(c, d.x, acc[4]); acc[5] = fmaf(c, d.y, acc[5]);
    acc[6] = fmaf(c, f.x, acc[6]); acc[7] = fmaf(c, f.y, acc[7]);
}

// pack two fp32 into one __half2 as uint
__device__ __forceinline__ uint32_t pack_h2(float lo, float hi) {
    __half2 h = __floats2half2_rn(lo, hi);
    return *(uint32_t*)&h;
}

// inline int64-vs-int32 detection: first 8 odd 32-bit words all zero <=> int64
// (high halves of small non-negative int64 node ids). For int32 node-id data
// the all-zero case is astronomically unlikely. One 64B sector, L1-resident.
__device__ __forceinline__ bool detect64(const int* __restrict__ p) {
    return (p[1] | p[3] | p[5] | p[7] | p[9] | p[11] | p[13] | p[15]) == 0;
}

// ---------------- kernels ----------------

// Pass 1: histogram with ONE packed 64-bit atomic per edge.
__global__ void k_convert(const void* __restrict__ idx,
                          const float* __restrict__ dist, int E) {
    int e = blockIdx.x * blockDim.x + threadIdx.x;
    if (e >= E) return;
    int c;
    if (detect64((const int*)idx)) c = (int)((const long long*)idx)[e + E];
    else                           c = ((const int*)idx)[e + E];
    float w = 1.0f / (dist[e] + 1e-6f);
    unsigned long long v = (1ULL << 48) +
        (unsigned long long)(w * PACK_SCALE + 0.5f);
    atomicAdd(&g_pack[c], v);
}

// Scan stage A: per-block sums of counts (extracted from packed histogram).
__global__ void k_bsum(int n) {
    int t = threadIdx.x;
    int i0 = blockIdx.x * 1024 + t * 4;
    int s = 0;
    if (i0 + 3 < n) {
        ulonglong2 a = *(const ulonglong2*)&g_pack[i0];
        ulonglong2 b = *(const ulonglong2*)&g_pack[i0 + 2];
        s = (int)(a.x >> 48) + (int)(a.y >> 48)
          + (int)(b.x >> 48) + (int)(b.y >> 48);
    } else {
        #pragma unroll
        for (int j = 0; j < 4; j++) {
            int i = i0 + j;
            if (i < n) s += (int)(g_pack[i] >> 48);
        }
    }
    #pragma unroll
    for (int off = 16; off > 0; off >>= 1)
        s += __shfl_down_sync(0xFFFFFFFFu, s, off);
    __shared__ int ws[8];
    if ((t & 31) == 0) ws[t >> 5] = s;
    __syncthreads();
    if (t == 0) {
        int tot = 0;
        #pragma unroll
        for (int k = 0; k < 8; k++) tot += ws[k];
        g_bsum[blockIdx.x] = tot;
    }
}

// Scan stage B (single-warp shfl scan of block sums) + fused per-node work:
// indptr/cursor, dinvw/dinv1 (self-loop folded), fp16 H0 build.
__global__ void k_fill(const float* __restrict__ x,
                       const float* __restrict__ dtr,
                       const float* __restrict__ npd,
                       const float* __restrict__ kp,
                       const float* __restrict__ kpp,
                       const float* __restrict__ imin,
                       const float* __restrict__ imax, int n, int nb) {
    __shared__ int sh[128];       // exclusive prefix of block sums
    __shared__ int shTotal;
    int t = threadIdx.x;
    if (t < 32) {                 // warp 0: scan up to 128 block sums
        int b0 = t * 4;
        int v0 = (b0 + 0 < nb) ? g_bsum[b0 + 0] : 0;
        int v1 = (b0 + 1 < nb) ? g_bsum[b0 + 1] : 0;
        int v2 = (b0 + 2 < nb) ? g_bsum[b0 + 2] : 0;
        int v3 = (b0 + 3 < nb) ? g_bsum[b0 + 3] : 0;
        int tsum = v0 + v1 + v2 + v3;
        int inc = tsum;
        #pragma unroll
        for (int off = 1; off < 32; off <<= 1) {
            int u = __shfl_up_sync(0xFFFFFFFFu, inc, off);
            if (t >= off) inc += u;
        }
        int run = inc - tsum;     // exclusive prefix of this lane's group
        sh[b0 + 0] = run; run += v0;
        sh[b0 + 1] = run; run += v1;
        sh[b0 + 2] = run; run += v2;
        sh[b0 + 3] = run;
        if (t == 31) shTotal = inc;
    }
    __syncthreads();
    int blockExcl = sh[blockIdx.x];
    int totalE = shTotal;

    int lane = t & 31;
    int warp = t >> 5;
    int i0 = blockIdx.x * 1024 + t * 4;

    unsigned long long pv[4];
    int c[4];
    #pragma unroll
    for (int j = 0; j < 4; j++) {
        int i = i0 + j;
        pv[j] = (i < n) ? g_pack[i] : 0ULL;
        c[j] = (int)(pv[j] >> 48);
    }
    int tsum = c[0] + c[1] + c[2] + c[3];

    int inc = tsum;
    #pragma unroll
    for (int off = 1; off < 32; off <<= 1) {
        int u = __shfl_up_sync(0xFFFFFFFFu, inc, off);
        if (lane >= off) inc += u;
    }
    __shared__ int wsum[8];
    if (lane == 31) wsum[warp] = inc;
    __syncthreads();
    int woff = 0;
    for (int k = 0; k < warp; k++) woff += wsum[k];

    int excl = blockExcl + woff + (inc - tsum);
    #pragma unroll
    for (int j = 0; j < 4; j++) {
        int i = i0 + j;
        if (i < n) {
            g_indptr[i] = excl;
            g_cursor[i] = excl;
            float degw = (float)(pv[j] & PACK_MASK) * PACK_INV;
            g_dinvw[i] = rsqrtf(degw + 1.0f);        // self-loop weight 1
            g_dinv1[i] = rsqrtf((float)c[j] + 1.f);
            float2 xv = ((const float2*)x)[i];
            uint4 h;
            h.x = pack_h2(xv.x, xv.y);
            h.y = pack_h2(dtr[i], npd[i]);
            h.z = pack_h2(kp[i], kpp[i]);
            h.w = pack_h2(imin[i], imax[i]);
            g_h0[i] = h;
            if (i == n - 1) g_indptr[n] = totalE;
            excl += c[j];
        }
    }
}

// Pass 2: place edges into CSR order with precomputed source-side coefficient.
__global__ void k_place(const void* __restrict__ idx,
                        const float* __restrict__ dist, int E) {
    int e = blockIdx.x * blockDim.x + threadIdx.x;
    if (e >= E) return;
    int r, c;
    if (detect64((const int*)idx)) {
        const long long* p = (const long long*)idx;
        r = (int)p[e];
        c = (int)p[e + E];
    } else {
        const int* p = (const int*)idx;
        r = p[e];
        c = p[e + E];
    }
    float w = 1.0f / (dist[e] + 1e-6f);
    int pos = atomicAdd(&g_cursor[c], 1);
    g_mw[pos] = make_int2(r, __float_as_int(g_dinvw[r] * w));
}

// Layer 1 fused: aggregate 8-feature fp16 H0 (warp per node, 8 edges/iter in
// two independent chains), then in-warp GEMM(8->64)+bias+softplus -> fp16 h1.
__global__ __launch_bounds__(256) void k_agg8_gemm1(
        const float* __restrict__ W1, const float* __restrict__ b1,
        __half* __restrict__ outH, int n) {
    __shared__ float w1s[8 * 64];
    __shared__ float b1s[64];
    int t = threadIdx.x;
    for (int i = t; i < 512; i += 256) w1s[i] = W1[i];
    if (t < 64) b1s[t] = b1[t];
    __syncthreads();

    const __half* h0h = (const __half*)g_h0;
    int w = (blockIdx.x * 256 + t) >> 5;
    if (w >= n) return;
    int lane = t & 31;
    int g = lane >> 3;
    int f = lane & 7;
    int beg = g_indptr[w], end = g_indptr[w + 1];
    float acc = 0.f;
    int e = beg;
    for (; e + 8 <= end; e += 8) {
        int2 m0 = __ldg(&g_mw[e + g]);
        int2 m1 = __ldg(&g_mw[e + 4 + g]);
        float v0 = __half2float(h0h[m0.x * 8 + f]);
        float v1 = __half2float(h0h[m1.x * 8 + f]);
        acc = fmaf(__int_as_float(m0.y), v0, acc);
        acc = fmaf(__int_as_float(m1.y), v1, acc);
    }
    for (; e < end; e += 4) {
        int ee = e + g;
        if (ee < end) {
            int2 m = __ldg(&g_mw[ee]);
            acc += __int_as_float(m.y) * __half2float(h0h[m.x * 8 + f]);
        }
    }
    acc += __shfl_xor_sync(0xFFFFFFFFu, acc, 8);
    acc += __shfl_xor_sync(0xFFFFFFFFu, acc, 16);
    float dv = g_dinvw[w];
    float self = __half2float(h0h[w * 8 + f]);
    float val = dv * (acc + dv * self);   // lane holds f = lane&7

    float a[8];
    #pragma unroll
    for (int k = 0; k < 8; k++) a[k] = __shfl_sync(0xFFFFFFFFu, val, k);

    float s0 = b1s[lane], s1 = b1s[lane + 32];
    #pragma unroll
    for (int k = 0; k < 8; k++) {
        s0 = fmaf(a[k], w1s[k * 64 + lane], s0);
        s1 = fmaf(a[k], w1s[k * 64 + lane + 32], s1);
    }
    outH[(size_t)w * 64 + lane]      = __float2half_rn(softplus_f(s0));
    outH[(size_t)w * 64 + lane + 32] = __float2half_rn(softplus_f(s1));
}

// Aggregate 64-feature fp16 table -> fp16 aggregate. Warp per node;
// 8 lanes per edge (uint4 = 8 features/lane), 8 edges in flight per
// iteration in two independent chains. fp32 accumulate, fp16 store.
__global__ __launch_bounds__(256) void k_agg64(
        const __half* __restrict__ h, __half* __restrict__ agg, int n) {
    int w = (blockIdx.x * blockDim.x + threadIdx.x) >> 5;
    if (w >= n) return;
    int lane = threadIdx.x & 31;
    int q = lane >> 3;        // quarter: which edge of the group
    int l8 = lane & 7;        // feature block: features [8*l8, 8*l8+8)
    int beg = g_indptr[w], end = g_indptr[w + 1];
    float acc[8] = {0.f, 0.f, 0.f, 0.f, 0.f, 0.f, 0.f, 0.f};
    int e = beg;
    for (; e + 8 <= end; e += 8) {
        int2 m0 = __ldg(&g_mw[e + q]);
        int2 m1 = __ldg(&g_mw[e + 4 + q]);
        uint4 u0 = __ldg((const uint4*)(h + (size_t)m0.x * 64) + l8);
        uint4 u1 = __ldg((const uint4*)(h + (size_t)m1.x * 64) + l8);
        acc8(acc, __int_as_float(m0.y), u0);
        acc8(acc, __int_as_float(m1.y), u1);
    }
    for (; e + 4 <= end; e += 4) {
        int2 m = __ldg(&g_mw[e + q]);
        uint4 u = __ldg((const uint4*)(h + (size_t)m.x * 64) + l8);
        acc8(acc, __int_as_float(m.y), u);
    }
    int rem = end - e;
    if (q < rem) {
        int2 m = __ldg(&g_mw[e + q]);
        uint4 u = __ldg((const uint4*)(h + (size_t)m.x * 64) + l8);
        acc8(acc, __int_as_float(m.y), u);
    }
    // reduce across the 4 quarters
    #pragma unroll
    for (int i = 0; i < 8; i++) {
        acc[i] += __shfl_xor_sync(0xFFFFFFFFu, acc[i], 8);
        acc[i] += __shfl_xor_sync(0xFFFFFFFFu, acc[i], 16);
    }
    if (q == 0) {
        float dv = g_dinvw[w];
        uint4 su = __ldg((const uint4*)(h + (size_t)w * 64) + l8);
        float2 sa = __half22float2(*(const __half2*)&su.x);
        float2 sb = __half22float2(*(const __half2*)&su.y);
        float2 sc = __half22float2(*(const __half2*)&su.z);
        float2 sd = __half22float2(*(const __half2*)&su.w);
        uint4 o;
        o.x = pack_h2(dv * (acc[0] + dv * sa.x), dv * (acc[1] + dv * sa.y));
        o.y = pack_h2(dv * (acc[2] + dv * sb.x), dv * (acc[3] + dv * sb.y));
        o.z = pack_h2(dv * (acc[4] + dv * sc.x), dv * (acc[5] + dv * sc.y));
        o.w = pack_h2(dv * (acc[6] + dv * sd.x), dv * (acc[7] + dv * sd.y));
        ((uint4*)(agg + (size_t)w * 64))[l8] = o;
    }
}

// GEMM [n,64](fp16) x [64,64] + bias + softplus -> fp16 table. W in registers,
// 8-row smem stages (fp16 expanded to fp32 on fill).
__global__ __launch_bounds__(256) void k_gemm64(
        const __half* __restrict__ in, const float* __restrict__ W,
        const float* __restrict__ b, __half* __restrict__ out, int n) {
    __shared__ float sIn[8 * 64];
    int o = threadIdx.x & 63;
    int nl = threadIdx.x >> 6;   // 0..3
    float wreg[64];
    #pragma unroll
    for (int f = 0; f < 64; f++) wreg[f] = W[f * 64 + o];
    float bias = b[o];
    int base = blockIdx.x * 128;
    for (int k = 0; k < 128; k += 8) {
        __syncthreads();
        if (threadIdx.x < 128) {
            int rr = threadIdx.x >> 4;
            int cc = threadIdx.x & 15;
            int node = base + k + rr;
            uint2 u = (node < n) ? __ldg((const uint2*)(in + (size_t)node * 64) + cc)
                                 : make_uint2(0u, 0u);
            float2 fa = __half22float2(*(const __half2*)&u.x);
            float2 fb = __half22float2(*(const __half2*)&u.y);
            ((float4*)sIn)[threadIdx.x] = make_float4(fa.x, fa.y, fb.x, fb.y);
        }
        __syncthreads();
        #pragma unroll
        for (int s = 0; s < 2; s++) {
            int r = nl + s * 4;
            int node = base + k + r;
            if (node < n) {
                float acc = bias;
                #pragma unroll
                for (int f = 0; f < 64; f++) acc = fmaf(sIn[r * 64 + f], wreg[f], acc);
                out[(size_t)node * 64 + o] = __float2half_rn(softplus_f(acc));
            }
        }
    }
}

// Layer-3 GEMM fused with the output projection (input fp16 aggregate):
// s1[node] = dinv1[node] * sum_o softplus(gemm_o) * Wout[o].
__global__ __launch_bounds__(256) void k_gemm_wout(
        const __half* __restrict__ in, const float* __restrict__ W,
        const float* __restrict__ b, const float* __restrict__ Wout, int n) {
    __shared__ float sIn[8 * 64];
    __shared__ float red[8];
    int o = threadIdx.x & 63;
    int nl = threadIdx.x >> 6;   // 0..3
    float wreg[64];
    #pragma unroll
    for (int f = 0; f < 64; f++) wreg[f] = W[f * 64 + o];
    float bias = b[o];
    float wo = Wout[o];
    int base = blockIdx.x * 128;
    for (int k = 0; k < 128; k += 8) {
        __syncthreads();
        if (threadIdx.x < 128) {
            int rr = threadIdx.x >> 4;
            int cc = threadIdx.x & 15;
            int node = base + k + rr;
            uint2 u = (node < n) ? __ldg((const uint2*)(in + (size_t)node * 64) + cc)
                                 : make_uint2(0u, 0u);
            float2 fa = __half22float2(*(const __half2*)&u.x);
            float2 fb = __half22float2(*(const __half2*)&u.y);
            ((float4*)sIn)[threadIdx.x] = make_float4(fa.x, fa.y, fb.x, fb.y);
        }
        __syncthreads();
        #pragma unroll
        for (int s = 0; s < 2; s++) {
            int r = nl + s * 4;
            int node = base + k + r;
            float part = 0.f;
            if (node < n) {
                float acc = bias;
                #pragma unroll
                for (int f = 0; f < 64; f++) acc = fmaf(sIn[r * 64 + f], wreg[f], acc);
                part = softplus_f(acc) * wo;
            }
            float ws = warp_sum(part);
            if ((threadIdx.x & 31) == 0) red[threadIdx.x >> 5] = ws;
            __syncthreads();
            if (o == 0 && node < n)
                g_s1[node] = g_dinv1[node] * (red[nl * 2] + red[nl * 2 + 1]);
            __syncthreads();
        }
    }
}

// out[n] = bout + dinv1[n] * (s1[n] + sum_e s1[row[e]])   (warp per node)
__global__ __launch_bounds__(256) void k_out(
        const float* __restrict__ bout, float* __restrict__ out, int n) {
    int w = (blockIdx.x * blockDim.x + threadIdx.x) >> 5;
    if (w >= n) return;
    int lane = threadIdx.x & 31;
    int beg = g_indptr[w], end = g_indptr[w + 1];
    float acc = 0.f;
    for (int e = beg + lane; e < end; e += 32) {
        int r = __ldg(&g_mw[e]).x;
        acc += g_s1[r];
    }
    acc = warp_sum(acc);
    if (lane == 0)
        out[w] = bout[0] + g_dinv1[w] * (acc + g_s1[w]);
}

// ---------------- launch ----------------
extern "C" void kernel_launch(void* const* d_in, const int* in_sizes, int n_in,
                              void* d_out, int out_size) {
    (void)n_in; (void)out_size;
    const void*  edge_idx = d_in[8];
    const float* edge_d   = (const float*)d_in[9];
    const float* x    = (const float*)d_in[1];
    const float* dtr  = (const float*)d_in[2];
    const float* npd  = (const float*)d_in[3];
    const float* kp   = (const float*)d_in[4];
    const float* kpp  = (const float*)d_in[5];
    const float* imin = (const float*)d_in[6];
    const float* imax = (const float*)d_in[7];
    const float* W1 = (const float*)d_in[10];
    const float* b1 = (const float*)d_in[11];
    const float* W2 = (const float*)d_in[12];
    const float* b2 = (const float*)d_in[13];
    const float* W3 = (const float*)d_in[14];
    const float* b3 = (const float*)d_in[15];
    const float* Wout = (const float*)d_in[16];
    const float* bout = (const float*)d_in[17];

    int N = in_sizes[1] / 2;          // x is [N,2]
    int E = in_sizes[9];              // edge_distance is [E]
    if (N > NMAX) N = NMAX;
    if (E > EMAX) E = EMAX;

    __half *pH = nullptr, *pAgg = nullptr;
    unsigned long long* pPack = nullptr;
    cudaGetSymbolAddress((void**)&pH, g_H);
    cudaGetSymbolAddress((void**)&pAgg, g_Agg);
    cudaGetSymbolAddress((void**)&pPack, g_pack);

    const int T = 256;
    int gE  = (E + T - 1) / T;
    int gW  = (N * 32 + T - 1) / T;       // warp-per-node kernels
    int gG  = (N + 127) / 128;            // gemm blocks
    int nb  = (N + 1023) / 1024;          // scan blocks

    cudaMemsetAsync(pPack, 0, (size_t)N * sizeof(unsigned long long));
    k_convert<<<gE, T>>>(edge_idx, edge_d, E);
    k_bsum<<<nb, 256>>>(N);
    k_fill<<<nb, 256>>>(x, dtr, npd, kp, kpp, imin, imax, N, nb);
    k_place<<<gE, T>>>(edge_idx, edge_d, E);

    // Layer 1: fused aggregate(8) + GEMM(8->64) + softplus -> fp16 table (h1)
    k_agg8_gemm1<<<gW, T>>>(W1, b1, pH, N);

    // Layer 2: gather fp16 h1 -> fp16 aggregate -> GEMM -> fp16 table (h2)
    k_agg64<<<gW, T>>>(pH, pAgg, N);
    k_gemm64<<<gG, 256>>>(pAgg, W2, b2, pH, N);

    // Layer 3: gather fp16 h2 -> fp16 aggregate -> GEMM + output projection
    k_agg64<<<gW, T>>>(pH, pAgg, N);
    k_gemm_wout<<<gG, 256>>>(pAgg, W3, b3, Wout, N);

    // Output conv aggregation with ones-norms
    k_out<<<gW, T>>>(bout, (float*)d_out, N);
}